// round 4
// baseline (speedup 1.0000x reference)
#include <cuda_runtime.h>

// out[b,h,w,c] = sum_j w[j,c] * t_j[b,h,w,c]
// Shapes: t_j = (8,128,128,128) fp32 contiguous; w = (5,128) fp32.
// N = 16,777,216 elements -> 4,194,304 float4 items. C=128 -> 32 float4 per row.
// Pure HBM-bound streaming kernel: 5 reads + 1 write = 384 MiB total traffic.

__global__ __launch_bounds__(256, 8)
void merge5_kernel(const float4* __restrict__ t1,
                   const float4* __restrict__ t2,
                   const float4* __restrict__ t3,
                   const float4* __restrict__ t4,
                   const float4* __restrict__ t5,
                   const float4* __restrict__ w,   // (5,32) float4 = (5,128) floats
                   float4* __restrict__ out,
                   int n4) {
    int idx = blockIdx.x * blockDim.x + threadIdx.x;
    if (idx >= n4) return;

    int cw = idx & 31;  // which float4 within the 128-channel row

    // Weight vectors: 2.5 KB table, L1-resident, warp-broadcast (lanes in a
    // warp cover 32 consecutive float4s -> each lane a distinct cw, conflict-free).
    float4 w0 = __ldg(&w[0 * 32 + cw]);
    float4 w1 = __ldg(&w[1 * 32 + cw]);
    float4 w2 = __ldg(&w[2 * 32 + cw]);
    float4 w3 = __ldg(&w[3 * 32 + cw]);
    float4 w4 = __ldg(&w[4 * 32 + cw]);

    // Front-batch the 5 independent 128-bit global loads for MLP=5/thread.
    float4 a = t1[idx];
    float4 b = t2[idx];
    float4 c = t3[idx];
    float4 d = t4[idx];
    float4 e = t5[idx];

    float4 o;
    o.x = a.x * w0.x + b.x * w1.x + c.x * w2.x + d.x * w3.x + e.x * w4.x;
    o.y = a.y * w0.y + b.y * w1.y + c.y * w2.y + d.y * w3.y + e.y * w4.y;
    o.z = a.z * w0.z + b.z * w1.z + c.z * w2.z + d.z * w3.z + e.z * w4.z;
    o.w = a.w * w0.w + b.w * w1.w + c.w * w2.w + d.w * w3.w + e.w * w4.w;

    out[idx] = o;
}

extern "C" void kernel_launch(void* const* d_in, const int* in_sizes, int n_in,
                              void* d_out, int out_size) {
    const float4* t1 = (const float4*)d_in[0];
    const float4* t2 = (const float4*)d_in[1];
    const float4* t3 = (const float4*)d_in[2];
    const float4* t4 = (const float4*)d_in[3];
    const float4* t5 = (const float4*)d_in[4];
    const float4* w  = (const float4*)d_in[5];
    float4* out = (float4*)d_out;

    int n4 = out_size / 4;  // 16,777,216 / 4 = 4,194,304
    int threads = 256;
    int blocks = (n4 + threads - 1) / threads;  // 16384 blocks
    merge5_kernel<<<blocks, threads>>>(t1, t2, t3, t4, t5, w, out, n4);
}